// round 5
// baseline (speedup 1.0000x reference)
#include <cuda_runtime.h>
#include <math.h>

#define HIN 228
#define WIN 304
#define HG 76
#define WG 102
#define NN 7752
#define BB 2
#define KK 16
#define NCH 8
#define CHSZ (NN / NCH)   // 969

// ---------------- scratch (device globals; no allocation allowed) ----------------
__device__ float g_pts0[BB * NN * 3];
__device__ float g_sq[BB * NN];
__device__ float g_g81[BB * NN * 81];
__device__ float g_hA[BB * NN * 96];
__device__ float g_hB[BB * NN * 96];
__device__ float g_h3[BB * NN * 9];
__device__ int   g_idx[BB * NN * KK];
__device__ float g_bd[BB * NN * NCH * KK];
__device__ int   g_bi[BB * NN * NCH * KK];
// transposed (and output-padded) weights: [c][o] layout
__device__ float g_wTe1[162 * 96];
__device__ float g_wTa1[162 * 96];
__device__ float g_wTe2[192 * 96];
__device__ float g_wTa2[192 * 96];
__device__ float g_wTe3[192 * 32];
__device__ float g_wTa3[192 * 32];

// XLA-GPU 16-element reduction tree (16 lanes/row emitter: shfl_down 8,4,2,1)
__device__ __forceinline__ float tree_sum16(const float* v) {
    float s8[8];
#pragma unroll
    for (int l = 0; l < 8; ++l) s8[l] = __fadd_rn(v[l], v[l + 8]);
    float s4[4];
#pragma unroll
    for (int l = 0; l < 4; ++l) s4[l] = __fadd_rn(s8[l], s8[l + 4]);
    float s2[2];
#pragma unroll
    for (int l = 0; l < 2; ++l) s2[l] = __fadd_rn(s4[l], s4[l + 2]);
    return __fadd_rn(s2[0], s2[1]);
}

// ---------------- build: depth fuse, loc points, guidance graph gather ----------------
__global__ void build_kernel(const float* __restrict__ guidance,
                             const float* __restrict__ ini,
                             const float* __restrict__ sparse,
                             float* __restrict__ pts,
                             float* __restrict__ sq,
                             float* __restrict__ g81) {
    int n = blockIdx.x * blockDim.x + threadIdx.x;
    int b = blockIdx.y;
    if (n >= NN) return;
    int i = n / WG;
    int j = n - i * WG;

    int rd = 3 * i + 1;
    int cd = 3 * j;
    int doff = (b * HIN + rd) * WIN + cd;
    float sp = sparse[doff];
    float iv = ini[doff];
    float mask = (sp > 0.f) ? 1.f : ((sp < 0.f) ? -1.f : 0.f);
    // d = (1-mask)*ini + mask*sparse, precise fp32 ops, no fma contraction
    float d = __fadd_rn(__fmul_rn(__fsub_rn(1.f, mask), iv), __fmul_rn(mask, sp));

    // camera in float32 (numpy weak-scalar semantics)
    const float cxf = 156.52237935402365f;   // 313.0447587080473/2
    const float fxf = 291.31224083868975f;   // 582.6244816773795/2
    const float cyf = 119.22194813310193f;   // 238.44389626620386/2
    const float fyf = 291.3455163549432f;    // 582.6910327098864/2
    float x3 = __fdiv_rn(__fsub_rn((float)j, cxf), fxf);
    float y3 = __fdiv_rn(__fsub_rn((float)i, cyf), fyf);
    float l0 = __fmul_rn(__fmul_rn(x3, d), 3.0f);
    float l1 = __fmul_rn(__fmul_rn(y3, d), 3.0f);
    float l2 = d;

    int base = b * NN + n;
    pts[base * 3 + 0] = l0;
    pts[base * 3 + 1] = l1;
    pts[base * 3 + 2] = l2;
    // XLA multi-row reduce (4 lanes/row): (x0^2 + x2^2) + x1^2, separate rounding
    float p0 = __fmul_rn(l0, l0);
    float p1 = __fmul_rn(l1, l1);
    float p2 = __fmul_rn(l2, l2);
    sq[base] = __fadd_rn(__fadd_rn(p0, p2), p1);

    const float* gb = guidance + (size_t)b * 81 * HIN * WIN;
    float* go = g81 + (size_t)base * 81;
#pragma unroll
    for (int c = 0; c < 81; ++c) {
        int r = 3 * i + (c / 9) - 3;
        int cc = 3 * j + (c % 9) - 4;
        float v = 0.f;
        if (r >= 0 && r < HIN && cc >= 0 && cc < WIN)
            v = gb[(c * HIN + r) * WIN + cc];
        go[c] = v;
    }
}

// ---------------- top-16 insertion (ascending dist; ties keep earlier index) ------
__device__ __forceinline__ void knn_insert(float dist, int index, float* bd, int* bi) {
    if (dist < bd[KK - 1]) {
        bd[KK - 1] = dist;
        bi[KK - 1] = index;
#pragma unroll
        for (int jj = KK - 1; jj > 0; --jj) {
            if (bd[jj] < bd[jj - 1]) {
                float td = bd[jj]; bd[jj] = bd[jj - 1]; bd[jj - 1] = td;
                int ti = bi[jj]; bi[jj] = bi[jj - 1]; bi[jj - 1] = ti;
            }
        }
    }
}

__device__ __forceinline__ float knn_dist(float qsq, float dot, float csq) {
    // reference: (sq - 2.0*dot) + sqT, precise fp32, no contraction
    return __fadd_rn(__fsub_rn(qsq, __fmul_rn(2.0f, dot)), csq);
}

// ---------------- KNN D=3, candidate-chunked ----------------
#define KNN_TILE 64

__global__ void __launch_bounds__(128) knn3_kernel(const float* __restrict__ pts,
                                                   const float* __restrict__ sqn,
                                                   float* __restrict__ bdo,
                                                   int* __restrict__ bio) {
    __shared__ float s_c[KNN_TILE * 3];
    __shared__ float s_sq[KNN_TILE];

    int b = blockIdx.z;
    int ch = blockIdx.y;
    int n = blockIdx.x * blockDim.x + threadIdx.x;
    bool valid = (n < NN);

    float q0 = 0.f, q1 = 0.f, q2 = 0.f, qsq = 0.f;
    if (valid) {
        size_t bn = (size_t)(b * NN + n);
        q0 = pts[bn * 3 + 0];
        q1 = pts[bn * 3 + 1];
        q2 = pts[bn * 3 + 2];
        qsq = sqn[bn];
    }

    float bd[KK]; int bi[KK];
#pragma unroll
    for (int k = 0; k < KK; ++k) { bd[k] = 3.0e38f; bi[k] = 0; }

    int mBeg = ch * CHSZ, mEnd = mBeg + CHSZ;
    for (int m0 = mBeg; m0 < mEnd; m0 += KNN_TILE) {
        __syncthreads();
        for (int t = threadIdx.x; t < KNN_TILE * 3; t += blockDim.x) {
            int mm = m0 + t / 3;
            s_c[t] = (mm < mEnd) ? pts[((size_t)b * NN + m0) * 3 + t] : 0.f;
        }
        for (int t = threadIdx.x; t < KNN_TILE; t += blockDim.x) {
            int mm = m0 + t;
            s_sq[t] = (mm < mEnd) ? sqn[b * NN + mm] : 3.0e38f;
        }
        __syncthreads();
        if (valid) {
#pragma unroll 4
            for (int t = 0; t < KNN_TILE; ++t) {
                // serial ascending FMA (cuBLAS k-order)
                float a = fmaf(q0, s_c[t * 3 + 0], 0.f);
                a = fmaf(q1, s_c[t * 3 + 1], a);
                a = fmaf(q2, s_c[t * 3 + 2], a);
                knn_insert(knn_dist(qsq, a, s_sq[t]), m0 + t, bd, bi);
            }
        }
    }
    if (valid) {
        size_t base = ((size_t)(b * NN + n) * NCH + ch) * KK;
#pragma unroll
        for (int k = 0; k < KK; ++k) { bdo[base + k] = bd[k]; bio[base + k] = bi[k]; }
    }
}

// ---------------- KNN D=96, candidate-chunked, serial-FMA dot ----------------
__global__ void __launch_bounds__(128) knn96_kernel(const float* __restrict__ pts,
                                                    const float* __restrict__ sqn,
                                                    float* __restrict__ bdo,
                                                    int* __restrict__ bio) {
    __shared__ __align__(16) float4 s_c[KNN_TILE][24];
    __shared__ float s_sq[KNN_TILE];

    int b = blockIdx.z;
    int ch = blockIdx.y;
    int n = blockIdx.x * blockDim.x + threadIdx.x;
    bool valid = (n < NN);

    float4 q[24];
    float qsq = 0.f;
    if (valid) {
        const float4* qp = reinterpret_cast<const float4*>(pts + (size_t)(b * NN + n) * 96);
#pragma unroll
        for (int c4 = 0; c4 < 24; ++c4) q[c4] = qp[c4];
        qsq = sqn[b * NN + n];
    } else {
#pragma unroll
        for (int c4 = 0; c4 < 24; ++c4) q[c4] = make_float4(0.f, 0.f, 0.f, 0.f);
    }

    float bd[KK]; int bi[KK];
#pragma unroll
    for (int k = 0; k < KK; ++k) { bd[k] = 3.0e38f; bi[k] = 0; }

    int mBeg = ch * CHSZ, mEnd = mBeg + CHSZ;
    for (int m0 = mBeg; m0 < mEnd; m0 += KNN_TILE) {
        __syncthreads();
        for (int t = threadIdx.x; t < KNN_TILE * 24; t += blockDim.x) {
            int mm = m0 + t / 24;
            s_c[t / 24][t % 24] = (mm < mEnd)
                ? reinterpret_cast<const float4*>(pts)[((size_t)b * NN + mm) * 24 + (t % 24)]
                : make_float4(0.f, 0.f, 0.f, 0.f);
        }
        for (int t = threadIdx.x; t < KNN_TILE; t += blockDim.x) {
            int mm = m0 + t;
            s_sq[t] = (mm < mEnd) ? sqn[b * NN + mm] : 3.0e38f;
        }
        __syncthreads();
        if (valid) {
            for (int t0 = 0; t0 < KNN_TILE; t0 += 4) {
                float a0 = 0.f, a1 = 0.f, a2 = 0.f, a3 = 0.f;
#pragma unroll
                for (int c4 = 0; c4 < 24; ++c4) {
                    float4 qv = q[c4];
                    float4 v0 = s_c[t0 + 0][c4];
                    float4 v1 = s_c[t0 + 1][c4];
                    float4 v2 = s_c[t0 + 2][c4];
                    float4 v3 = s_c[t0 + 3][c4];
                    // each candidate: strictly serial ascending FMA chain
                    a0 = fmaf(qv.x, v0.x, a0); a0 = fmaf(qv.y, v0.y, a0);
                    a0 = fmaf(qv.z, v0.z, a0); a0 = fmaf(qv.w, v0.w, a0);
                    a1 = fmaf(qv.x, v1.x, a1); a1 = fmaf(qv.y, v1.y, a1);
                    a1 = fmaf(qv.z, v1.z, a1); a1 = fmaf(qv.w, v1.w, a1);
                    a2 = fmaf(qv.x, v2.x, a2); a2 = fmaf(qv.y, v2.y, a2);
                    a2 = fmaf(qv.z, v2.z, a2); a2 = fmaf(qv.w, v2.w, a2);
                    a3 = fmaf(qv.x, v3.x, a3); a3 = fmaf(qv.y, v3.y, a3);
                    a3 = fmaf(qv.z, v3.z, a3); a3 = fmaf(qv.w, v3.w, a3);
                }
                knn_insert(knn_dist(qsq, a0, s_sq[t0 + 0]), m0 + t0 + 0, bd, bi);
                knn_insert(knn_dist(qsq, a1, s_sq[t0 + 1]), m0 + t0 + 1, bd, bi);
                knn_insert(knn_dist(qsq, a2, s_sq[t0 + 2]), m0 + t0 + 2, bd, bi);
                knn_insert(knn_dist(qsq, a3, s_sq[t0 + 3]), m0 + t0 + 3, bd, bi);
            }
        }
    }
    if (valid) {
        size_t base = ((size_t)(b * NN + n) * NCH + ch) * KK;
#pragma unroll
        for (int k = 0; k < KK; ++k) { bdo[base + k] = bd[k]; bio[base + k] = bi[k]; }
    }
}

// ---------------- stable 8-way merge of per-chunk top-16 lists ----------------
__global__ void knn_merge_kernel(const float* __restrict__ bdall,
                                 const int* __restrict__ biall,
                                 int* __restrict__ out) {
    int q = blockIdx.x * blockDim.x + threadIdx.x;
    if (q >= BB * NN) return;
    int p[NCH];
#pragma unroll
    for (int ch = 0; ch < NCH; ++ch) p[ch] = 0;
    size_t base = (size_t)q * NCH * KK;
#pragma unroll
    for (int s = 0; s < KK; ++s) {
        float best = 3.4e38f;
        int bch = 0;
#pragma unroll
        for (int ch = 0; ch < NCH; ++ch) {
            float dv = bdall[base + ch * KK + p[ch]];
            if (dv < best) { best = dv; bch = ch; }  // strict <: earlier chunk (lower idx) wins ties
        }
        out[(size_t)q * KK + s] = biall[base + bch * KK + p[bch]];
        p[bch]++;
    }
}

// ---------------- weight transpose (+pad output dim) ----------------
__global__ void transpose_w_kernel(const float* __restrict__ w, float* __restrict__ wT,
                                   int C2, int O, int OP) {
    int t = blockIdx.x * blockDim.x + threadIdx.x;
    if (t >= C2 * OP) return;
    int c = t / OP;
    int o = t - c * OP;
    wT[t] = (o < O) ? w[o * C2 + c] : 0.f;
}

// ---------------- faithful per-edge attention layer ----------------
// e[edge][o] = serial ascending FMA over c (cuBLAS order), bias after;
// softmax: expf (libdevice), sums via XLA 16-lane reduction tree;
// out = tree_sum16 of e_k * (exp_k / S).
template <int C, int O, int OP>
__global__ void edge_attn_kernel(const float* __restrict__ X,
                                 const int* __restrict__ idx,
                                 const float* __restrict__ weT, const float* __restrict__ be,
                                 const float* __restrict__ waT, const float* __restrict__ ba,
                                 float* __restrict__ out) {
    constexpr int C2 = 2 * C;
    constexpr int NW = OP / 32;
    __shared__ float sh_h[2][KK][C2];
    __shared__ float sh_e[2][KK][OP];
    __shared__ float sh_a[2][KK][OP];

    int b = blockIdx.y;
    int n0 = blockIdx.x * 2;
    int tid = threadIdx.x;

    // build h rows in smem
    for (int t = tid; t < 2 * KK * C; t += blockDim.x) {
        int nodeL = t / (KK * C);
        int r = t - nodeL * (KK * C);
        int k = r / C;
        int c = r - k * C;
        int n = n0 + nodeL;
        size_t bn = (size_t)(b * NN + n);
        float xi = X[bn * C + c];
        int j = idx[bn * KK + k];
        float xj = X[((size_t)(b * NN + j)) * C + c];
        sh_h[nodeL][k][c] = xi;
        sh_h[nodeL][k][C + c] = __fsub_rn(xj, xi);
    }
    __syncthreads();

    int warp = tid >> 5, lane = tid & 31;
    int nodeL = warp / NW;
    int og = (warp % NW) * 32 + lane;

    float accE[KK], accA[KK];
#pragma unroll
    for (int k = 0; k < KK; ++k) { accE[k] = 0.f; accA[k] = 0.f; }

    for (int c = 0; c < C2; ++c) {
        float we = __ldg(&weT[c * OP + og]);
        float wa = __ldg(&waT[c * OP + og]);
#pragma unroll
        for (int k = 0; k < KK; ++k) {
            float hv = sh_h[nodeL][k][c];   // warp-broadcast LDS
            accE[k] = fmaf(we, hv, accE[k]);
            accA[k] = fmaf(wa, hv, accA[k]);
        }
    }
    float eb = (og < O) ? __ldg(&be[og]) : 0.f;
    float ab = (og < O) ? __ldg(&ba[og]) : 0.f;
#pragma unroll
    for (int k = 0; k < KK; ++k) {
        sh_e[nodeL][k][og] = __fadd_rn(accE[k], eb);
        sh_a[nodeL][k][og] = __fadd_rn(accA[k], ab);
    }
    __syncthreads();

    if (tid < 2 * O) {
        int nl = tid / O;
        int o = tid - nl * O;
        int n = n0 + nl;
        float la[KK], ex[KK], ea[KK];
#pragma unroll
        for (int k = 0; k < KK; ++k) la[k] = sh_a[nl][k][o];
        float m = la[0];
#pragma unroll
        for (int k = 1; k < KK; ++k) m = fmaxf(m, la[k]);
#pragma unroll
        for (int k = 0; k < KK; ++k)
            ex[k] = expf(__fsub_rn(la[k], m));   // libdevice __nv_expf = XLA GPU exp
        float S = tree_sum16(ex);
#pragma unroll
        for (int k = 0; k < KK; ++k) {
            float av = __fdiv_rn(ex[k], S);
            ea[k] = __fmul_rn(sh_e[nl][k][o], av);
        }
        out[((size_t)(b * NN + n)) * O + o] = tree_sum16(ea);
    }
}

// ---------------- squared norms for 96-d features: XLA warp row-reduction ----------------
// lane l: ((x[l]^2 + x[l+32]^2) + x[l+64]^2), then shfl_down tree 16,8,4,2,1
__global__ void __launch_bounds__(256) sqnorm96_kernel(const float* __restrict__ h,
                                                       float* __restrict__ sq) {
    int warp = (blockIdx.x * blockDim.x + threadIdx.x) >> 5;
    int lane = threadIdx.x & 31;
    if (warp >= BB * NN) return;
    const float* r = h + (size_t)warp * 96;
    float x0 = r[lane], x1 = r[lane + 32], x2 = r[lane + 64];
    float p = __fadd_rn(__fadd_rn(__fmul_rn(x0, x0), __fmul_rn(x1, x1)), __fmul_rn(x2, x2));
#pragma unroll
    for (int off = 16; off > 0; off >>= 1)
        p = __fadd_rn(p, __shfl_down_sync(0xffffffffu, p, off));
    if (lane == 0) sq[warp] = p;
}

// ---------------- final pixel-shuffle + column slice ----------------
__global__ void final_kernel(const float* __restrict__ h3, float* __restrict__ out) {
    int t = blockIdx.x * blockDim.x + threadIdx.x;
    if (t >= BB * HIN * WIN) return;
    int w = t % WIN;
    int row = (t / WIN) % HIN;
    int b = t / (WIN * HIN);
    int col = w + 1;            // slice [:, :, :, 1:1+WIN]
    int j = col / 3, s = col % 3;
    int i = row / 3, r = row % 3;
    int ch = r * 3 + s;
    out[t] = h3[((size_t)(b * NN) + i * WG + j) * 9 + ch];
}

// ---------------- launch ----------------
#define GETSYM(p, sym) do { void* _tmp; cudaGetSymbolAddress(&_tmp, sym); p = _tmp; } while (0)

extern "C" void kernel_launch(void* const* d_in, const int* in_sizes, int n_in,
                              void* d_out, int out_size) {
    const float* guidance = (const float*)d_in[0];
    const float* ini      = (const float*)d_in[1];
    const float* sparse   = (const float*)d_in[2];
    const float* e_w1 = (const float*)d_in[3];
    const float* e_b1 = (const float*)d_in[4];
    const float* a_w1 = (const float*)d_in[5];
    const float* a_b1 = (const float*)d_in[6];
    const float* e_w2 = (const float*)d_in[7];
    const float* e_b2 = (const float*)d_in[8];
    const float* a_w2 = (const float*)d_in[9];
    const float* a_b2 = (const float*)d_in[10];
    const float* e_w3 = (const float*)d_in[11];
    const float* e_b3 = (const float*)d_in[12];
    const float* a_w3 = (const float*)d_in[13];
    const float* a_b3 = (const float*)d_in[14];
    float* out = (float*)d_out;

    void *p_pts0, *p_sq, *p_g81, *p_hA, *p_hB, *p_h3, *p_idx, *p_bd, *p_bi;
    void *p_wTe1, *p_wTa1, *p_wTe2, *p_wTa2, *p_wTe3, *p_wTa3;
    GETSYM(p_pts0, g_pts0); GETSYM(p_sq, g_sq); GETSYM(p_g81, g_g81);
    GETSYM(p_hA, g_hA); GETSYM(p_hB, g_hB); GETSYM(p_h3, g_h3); GETSYM(p_idx, g_idx);
    GETSYM(p_bd, g_bd); GETSYM(p_bi, g_bi);
    GETSYM(p_wTe1, g_wTe1); GETSYM(p_wTa1, g_wTa1);
    GETSYM(p_wTe2, g_wTe2); GETSYM(p_wTa2, g_wTa2);
    GETSYM(p_wTe3, g_wTe3); GETSYM(p_wTa3, g_wTa3);

    float* pts0 = (float*)p_pts0;  float* sqv = (float*)p_sq;  float* g81 = (float*)p_g81;
    float* hA = (float*)p_hA;      float* hB = (float*)p_hB;   float* h3 = (float*)p_h3;
    int* idxb = (int*)p_idx;
    float* bd = (float*)p_bd;      int* bi = (int*)p_bi;
    float* wTe1 = (float*)p_wTe1;  float* wTa1 = (float*)p_wTa1;
    float* wTe2 = (float*)p_wTe2;  float* wTa2 = (float*)p_wTa2;
    float* wTe3 = (float*)p_wTe3;  float* wTa3 = (float*)p_wTa3;

    // weight transposes (tiny)
    transpose_w_kernel<<<(162 * 96 + 255) / 256, 256>>>(e_w1, wTe1, 162, 96, 96);
    transpose_w_kernel<<<(162 * 96 + 255) / 256, 256>>>(a_w1, wTa1, 162, 96, 96);
    transpose_w_kernel<<<(192 * 96 + 255) / 256, 256>>>(e_w2, wTe2, 192, 96, 96);
    transpose_w_kernel<<<(192 * 96 + 255) / 256, 256>>>(a_w2, wTa2, 192, 96, 96);
    transpose_w_kernel<<<(192 * 32 + 255) / 256, 256>>>(e_w3, wTe3, 192, 9, 32);
    transpose_w_kernel<<<(192 * 32 + 255) / 256, 256>>>(a_w3, wTa3, 192, 9, 32);

    dim3 gN((NN + 127) / 128, BB);
    build_kernel<<<gN, 128>>>(guidance, ini, sparse, pts0, sqv, g81);

    dim3 gK((NN + 127) / 128, NCH, BB);
    dim3 gM((BB * NN + 127) / 128);
    dim3 gS((BB * NN * 32 + 255) / 256);
    dim3 gE(NN / 2, BB);

    // layer 1
    knn3_kernel<<<gK, 128>>>(pts0, sqv, bd, bi);
    knn_merge_kernel<<<gM, 128>>>(bd, bi, idxb);
    edge_attn_kernel<81, 96, 96><<<gE, 192>>>(g81, idxb, wTe1, e_b1, wTa1, a_b1, hA);

    // layer 2
    sqnorm96_kernel<<<gS, 256>>>(hA, sqv);
    knn96_kernel<<<gK, 128>>>(hA, sqv, bd, bi);
    knn_merge_kernel<<<gM, 128>>>(bd, bi, idxb);
    edge_attn_kernel<96, 96, 96><<<gE, 192>>>(hA, idxb, wTe2, e_b2, wTa2, a_b2, hB);

    // layer 3
    sqnorm96_kernel<<<gS, 256>>>(hB, sqv);
    knn96_kernel<<<gK, 128>>>(hB, sqv, bd, bi);
    knn_merge_kernel<<<gM, 128>>>(bd, bi, idxb);
    edge_attn_kernel<96, 9, 32><<<gE, 64>>>(hB, idxb, wTe3, e_b3, wTa3, a_b3, h3);

    // output
    final_kernel<<<(BB * HIN * WIN + 255) / 256, 256>>>(h3, out);
}

// round 6
// speedup vs baseline: 1.5533x; 1.5533x over previous
#include <cuda_runtime.h>
#include <math.h>

#define HIN 228
#define WIN 304
#define HG 76
#define WG 102
#define NN 7752
#define BB 2
#define KK 16
#define NCH 8
#define CHSZ (NN / NCH)   // 969
#define DT 61             // 61*128 >= 7752 dist tiles

// ---------------- scratch (device globals; no allocation allowed) ----------------
__device__ float g_pts0[BB * NN * 3];
__device__ float g_sq[BB * NN];
__device__ float g_g81[BB * NN * 81];
__device__ float g_hA[BB * NN * 96];
__device__ float g_hB[BB * NN * 96];
__device__ float g_h3[BB * NN * 9];
__device__ int   g_idx[BB * NN * KK];
__device__ float g_bd[BB * NN * NCH * KK];
__device__ int   g_bi[BB * NN * NCH * KK];
__device__ float g_dist[(size_t)BB * NN * NN];   // D[b][m][q] = dist(query q, cand m)
// interleaved transposed weights: [c][o] -> (we, wa)
__device__ float2 g_wEA1[162 * 96];
__device__ float2 g_wEA2[192 * 96];
__device__ float2 g_wEA3[192 * 32];

// XLA-GPU 16-element reduction tree
__device__ __forceinline__ float tree_sum16(const float* v) {
    float s8[8];
#pragma unroll
    for (int l = 0; l < 8; ++l) s8[l] = __fadd_rn(v[l], v[l + 8]);
    float s4[4];
#pragma unroll
    for (int l = 0; l < 4; ++l) s4[l] = __fadd_rn(s8[l], s8[l + 4]);
    float s2[2];
#pragma unroll
    for (int l = 0; l < 2; ++l) s2[l] = __fadd_rn(s4[l], s4[l + 2]);
    return __fadd_rn(s2[0], s2[1]);
}

// ---------------- build: depth fuse, loc points, guidance graph gather ----------------
__global__ void build_kernel(const float* __restrict__ guidance,
                             const float* __restrict__ ini,
                             const float* __restrict__ sparse,
                             float* __restrict__ pts,
                             float* __restrict__ sq,
                             float* __restrict__ g81) {
    int n = blockIdx.x * blockDim.x + threadIdx.x;
    int b = blockIdx.y;
    if (n >= NN) return;
    int i = n / WG;
    int j = n - i * WG;

    int rd = 3 * i + 1;
    int cd = 3 * j;
    int doff = (b * HIN + rd) * WIN + cd;
    float sp = sparse[doff];
    float iv = ini[doff];
    float mask = (sp > 0.f) ? 1.f : ((sp < 0.f) ? -1.f : 0.f);
    float d = __fadd_rn(__fmul_rn(__fsub_rn(1.f, mask), iv), __fmul_rn(mask, sp));

    const float cxf = 156.52237935402365f;
    const float fxf = 291.31224083868975f;
    const float cyf = 119.22194813310193f;
    const float fyf = 291.3455163549432f;
    float x3 = __fdiv_rn(__fsub_rn((float)j, cxf), fxf);
    float y3 = __fdiv_rn(__fsub_rn((float)i, cyf), fyf);
    float l0 = __fmul_rn(__fmul_rn(x3, d), 3.0f);
    float l1 = __fmul_rn(__fmul_rn(y3, d), 3.0f);
    float l2 = d;

    int base = b * NN + n;
    pts[base * 3 + 0] = l0;
    pts[base * 3 + 1] = l1;
    pts[base * 3 + 2] = l2;
    float p0 = __fmul_rn(l0, l0);
    float p1 = __fmul_rn(l1, l1);
    float p2 = __fmul_rn(l2, l2);
    sq[base] = __fadd_rn(__fadd_rn(p0, p2), p1);

    const float* gb = guidance + (size_t)b * 81 * HIN * WIN;
    float* go = g81 + (size_t)base * 81;
#pragma unroll
    for (int c = 0; c < 81; ++c) {
        int r = 3 * i + (c / 9) - 3;
        int cc = 3 * j + (c % 9) - 4;
        float v = 0.f;
        if (r >= 0 && r < HIN && cc >= 0 && cc < WIN)
            v = gb[(c * HIN + r) * WIN + cc];
        go[c] = v;
    }
}

// ---------------- top-16 insertion (ascending dist; ties keep earlier index) ------
__device__ __forceinline__ void knn_insert(float dist, int index, float* bd, int* bi) {
    if (dist < bd[KK - 1]) {
        bd[KK - 1] = dist;
        bi[KK - 1] = index;
#pragma unroll
        for (int jj = KK - 1; jj > 0; --jj) {
            if (bd[jj] < bd[jj - 1]) {
                float td = bd[jj]; bd[jj] = bd[jj - 1]; bd[jj - 1] = td;
                int ti = bi[jj]; bi[jj] = bi[jj - 1]; bi[jj - 1] = ti;
            }
        }
    }
}

__device__ __forceinline__ float knn_dist(float qsq, float dot, float csq) {
    return __fadd_rn(__fsub_rn(qsq, __fmul_rn(2.0f, dot)), csq);
}

// ---------------- KNN D=3, candidate-chunked (cheap; direct) ----------------
#define KNN_TILE 64

__global__ void __launch_bounds__(128) knn3_kernel(const float* __restrict__ pts,
                                                   const float* __restrict__ sqn,
                                                   float* __restrict__ bdo,
                                                   int* __restrict__ bio) {
    __shared__ float s_c[KNN_TILE * 3];
    __shared__ float s_sq[KNN_TILE];

    int b = blockIdx.z;
    int ch = blockIdx.y;
    int n = blockIdx.x * blockDim.x + threadIdx.x;
    bool valid = (n < NN);

    float q0 = 0.f, q1 = 0.f, q2 = 0.f, qsq = 0.f;
    if (valid) {
        size_t bn = (size_t)(b * NN + n);
        q0 = pts[bn * 3 + 0];
        q1 = pts[bn * 3 + 1];
        q2 = pts[bn * 3 + 2];
        qsq = sqn[bn];
    }

    float bd[KK]; int bi[KK];
#pragma unroll
    for (int k = 0; k < KK; ++k) { bd[k] = 3.0e38f; bi[k] = 0; }

    int mBeg = ch * CHSZ, mEnd = mBeg + CHSZ;
    for (int m0 = mBeg; m0 < mEnd; m0 += KNN_TILE) {
        __syncthreads();
        for (int t = threadIdx.x; t < KNN_TILE * 3; t += blockDim.x) {
            int mm = m0 + t / 3;
            s_c[t] = (mm < mEnd) ? pts[((size_t)b * NN + m0) * 3 + t] : 0.f;
        }
        for (int t = threadIdx.x; t < KNN_TILE; t += blockDim.x) {
            int mm = m0 + t;
            s_sq[t] = (mm < mEnd) ? sqn[b * NN + mm] : 3.0e38f;
        }
        __syncthreads();
        if (valid) {
#pragma unroll 4
            for (int t = 0; t < KNN_TILE; ++t) {
                float a = fmaf(q0, s_c[t * 3 + 0], 0.f);
                a = fmaf(q1, s_c[t * 3 + 1], a);
                a = fmaf(q2, s_c[t * 3 + 2], a);
                knn_insert(knn_dist(qsq, a, s_sq[t]), m0 + t, bd, bi);
            }
        }
    }
    if (valid) {
        size_t base = ((size_t)(b * NN + n) * NCH + ch) * KK;
#pragma unroll
        for (int k = 0; k < KK; ++k) { bdo[base + k] = bd[k]; bio[base + k] = bi[k]; }
    }
}

// ---------------- KNN96 phase 1: symmetric distance matrix (tiles ti<=tj) ----------------
__global__ void __launch_bounds__(128) knn96_dist_kernel(const float* __restrict__ pts,
                                                         const float* __restrict__ sqn,
                                                         float* __restrict__ D) {
    int b = blockIdx.z;
    int ti = blockIdx.y, tj = blockIdx.x;
    if (tj < ti) return;
    __shared__ __align__(16) float4 s_c[128][24];
    __shared__ float s_csq[128];
    int I = ti * 128, J = tj * 128;
    int tid = threadIdx.x;

    for (int t = tid; t < 128 * 24; t += 128) {
        int mm = J + t / 24;
        int mc = (mm < NN) ? mm : (NN - 1);
        s_c[t / 24][t % 24] =
            reinterpret_cast<const float4*>(pts)[((size_t)b * NN + mc) * 24 + (t % 24)];
    }
    {
        int mm = J + tid;
        s_csq[tid] = (mm < NN) ? sqn[b * NN + mm] : 0.f;
    }
    __syncthreads();

    int qi = I + tid;
    if (qi >= NN) return;   // no further block-wide syncs

    float4 q[24];
    const float4* qp = reinterpret_cast<const float4*>(pts + (size_t)(b * NN + qi) * 96);
#pragma unroll
    for (int c4 = 0; c4 < 24; ++c4) q[c4] = qp[c4];
    float qsq = sqn[b * NN + qi];

    float* Db = D + (size_t)b * NN * NN;

    for (int j0 = 0; j0 < 128; j0 += 4) {
        float a0 = 0.f, a1 = 0.f, a2 = 0.f, a3 = 0.f;
#pragma unroll
        for (int c4 = 0; c4 < 24; ++c4) {
            float4 qv = q[c4];
            float4 v0 = s_c[j0 + 0][c4];
            float4 v1 = s_c[j0 + 1][c4];
            float4 v2 = s_c[j0 + 2][c4];
            float4 v3 = s_c[j0 + 3][c4];
            a0 = fmaf(qv.x, v0.x, a0); a0 = fmaf(qv.y, v0.y, a0);
            a0 = fmaf(qv.z, v0.z, a0); a0 = fmaf(qv.w, v0.w, a0);
            a1 = fmaf(qv.x, v1.x, a1); a1 = fmaf(qv.y, v1.y, a1);
            a1 = fmaf(qv.z, v1.z, a1); a1 = fmaf(qv.w, v1.w, a1);
            a2 = fmaf(qv.x, v2.x, a2); a2 = fmaf(qv.y, v2.y, a2);
            a2 = fmaf(qv.z, v2.z, a2); a2 = fmaf(qv.w, v2.w, a2);
            a3 = fmaf(qv.x, v3.x, a3); a3 = fmaf(qv.y, v3.y, a3);
            a3 = fmaf(qv.z, v3.z, a3); a3 = fmaf(qv.w, v3.w, a3);
        }
        int m0 = J + j0;
        // orientation 1: query = qi, cand = m  ->  D[m][qi]
        if (m0 + 0 < NN) Db[(size_t)(m0 + 0) * NN + qi] = knn_dist(qsq, a0, s_csq[j0 + 0]);
        if (m0 + 1 < NN) Db[(size_t)(m0 + 1) * NN + qi] = knn_dist(qsq, a1, s_csq[j0 + 1]);
        if (m0 + 2 < NN) Db[(size_t)(m0 + 2) * NN + qi] = knn_dist(qsq, a2, s_csq[j0 + 2]);
        if (m0 + 3 < NN) Db[(size_t)(m0 + 3) * NN + qi] = knn_dist(qsq, a3, s_csq[j0 + 3]);
        // orientation 2: query = m, cand = qi  ->  D[qi][m]
        float e0 = knn_dist(s_csq[j0 + 0], a0, qsq);
        float e1 = knn_dist(s_csq[j0 + 1], a1, qsq);
        float e2 = knn_dist(s_csq[j0 + 2], a2, qsq);
        float e3 = knn_dist(s_csq[j0 + 3], a3, qsq);
        if (m0 + 3 < NN) {
            float4 st = make_float4(e0, e1, e2, e3);
            *reinterpret_cast<float4*>(&Db[(size_t)qi * NN + m0]) = st;
        } else {
            if (m0 + 0 < NN) Db[(size_t)qi * NN + m0 + 0] = e0;
            if (m0 + 1 < NN) Db[(size_t)qi * NN + m0 + 1] = e1;
            if (m0 + 2 < NN) Db[(size_t)qi * NN + m0 + 2] = e2;
        }
    }
}

// ---------------- KNN96 phase 2: chunked top-16 selection over D rows ----------------
__global__ void __launch_bounds__(128) knn96_select_kernel(const float* __restrict__ D,
                                                           float* __restrict__ bdo,
                                                           int* __restrict__ bio) {
    int b = blockIdx.z, ch = blockIdx.y;
    int n = blockIdx.x * blockDim.x + threadIdx.x;
    if (n >= NN) return;
    const float* Db = D + (size_t)b * NN * NN;

    float bd[KK]; int bi[KK];
#pragma unroll
    for (int k = 0; k < KK; ++k) { bd[k] = 3.0e38f; bi[k] = 0; }

    int mBeg = ch * CHSZ, mEnd = mBeg + CHSZ;
    int m = mBeg;
    for (; m + 4 <= mEnd; m += 4) {
        float d0 = Db[(size_t)(m + 0) * NN + n];
        float d1 = Db[(size_t)(m + 1) * NN + n];
        float d2 = Db[(size_t)(m + 2) * NN + n];
        float d3 = Db[(size_t)(m + 3) * NN + n];
        knn_insert(d0, m + 0, bd, bi);
        knn_insert(d1, m + 1, bd, bi);
        knn_insert(d2, m + 2, bd, bi);
        knn_insert(d3, m + 3, bd, bi);
    }
    for (; m < mEnd; ++m)
        knn_insert(Db[(size_t)m * NN + n], m, bd, bi);

    size_t base = ((size_t)(b * NN + n) * NCH + ch) * KK;
#pragma unroll
    for (int k = 0; k < KK; ++k) { bdo[base + k] = bd[k]; bio[base + k] = bi[k]; }
}

// ---------------- stable 8-way merge of per-chunk top-16 lists ----------------
__global__ void knn_merge_kernel(const float* __restrict__ bdall,
                                 const int* __restrict__ biall,
                                 int* __restrict__ out) {
    int q = blockIdx.x * blockDim.x + threadIdx.x;
    if (q >= BB * NN) return;
    int p[NCH];
#pragma unroll
    for (int ch = 0; ch < NCH; ++ch) p[ch] = 0;
    size_t base = (size_t)q * NCH * KK;
#pragma unroll
    for (int s = 0; s < KK; ++s) {
        float best = 3.4e38f;
        int bch = 0;
#pragma unroll
        for (int ch = 0; ch < NCH; ++ch) {
            float dv = bdall[base + ch * KK + p[ch]];
            if (dv < best) { best = dv; bch = ch; }
        }
        out[(size_t)q * KK + s] = biall[base + bch * KK + p[bch]];
        p[bch]++;
    }
}

// ---------------- weight transpose -> interleaved (we, wa), pad output dim ----------------
__global__ void transpose_w2_kernel(const float* __restrict__ we, const float* __restrict__ wa,
                                    float2* __restrict__ wEA, int C2, int O, int OP) {
    int t = blockIdx.x * blockDim.x + threadIdx.x;
    if (t >= C2 * OP) return;
    int c = t / OP;
    int o = t - c * OP;
    float2 v;
    v.x = (o < O) ? we[o * C2 + c] : 0.f;
    v.y = (o < O) ? wa[o * C2 + c] : 0.f;
    wEA[t] = v;
}

// ---------------- per-edge attention with bitwise prefix-halving ----------------
// Full chain per edge: acc = serial FMA over c=0..2C-1 of W[o][c]*h[c],
// where h[0..C-1] = x_i (same for all k) -> prefix computed once per (node,o),
// then continued over c=C..2C-1 with hd = x_j - x_i. Bitwise identical to the
// full chain. Softmax tail: libdevice expf + XLA 16-lane tree sums.
template <int C, int O, int OP>
__global__ void edge_attn_kernel(const float* __restrict__ X,
                                 const int* __restrict__ idx,
                                 const float2* __restrict__ wEA,
                                 const float* __restrict__ be,
                                 const float* __restrict__ ba,
                                 float* __restrict__ out) {
    constexpr int NW = OP / 32;
    constexpr int C4 = C / 4;
    constexpr int CR = C - C4 * 4;
    constexpr int CP = C4 * 4 + (CR ? 4 : 0);
    __shared__ __align__(16) float sh_xi[2][CP];
    __shared__ __align__(16) float sh_hd[2][KK][CP];
    __shared__ float sh_e[2][KK][OP];
    __shared__ float sh_a[2][KK][OP];

    int b = blockIdx.y;
    int n0 = blockIdx.x * 2;
    int tid = threadIdx.x;

    for (int t = tid; t < 2 * C; t += blockDim.x) {
        int nodeL = t / C, c = t - nodeL * C;
        sh_xi[nodeL][c] = X[((size_t)(b * NN + n0 + nodeL)) * C + c];
    }
    for (int t = tid; t < 2 * KK * C; t += blockDim.x) {
        int nodeL = t / (KK * C);
        int r = t - nodeL * (KK * C);
        int k = r / C, c = r - k * C;
        size_t bn = (size_t)(b * NN + n0 + nodeL);
        float xi = X[bn * C + c];
        int j = idx[bn * KK + k];
        sh_hd[nodeL][k][c] = __fsub_rn(X[((size_t)(b * NN + j)) * C + c], xi);
    }
    __syncthreads();

    int warp = tid >> 5, lane = tid & 31;
    int nodeL = warp / NW;
    int og = (warp % NW) * 32 + lane;

    // prefix: serial ascending c = 0..C-1 over x_i
    float pe = 0.f, pa = 0.f;
    for (int c = 0; c < C; ++c) {
        float2 w = __ldg(&wEA[c * OP + og]);
        float xv = sh_xi[nodeL][c];
        pe = fmaf(w.x, xv, pe);
        pa = fmaf(w.y, xv, pa);
    }

    float accE[KK], accA[KK];
#pragma unroll
    for (int k = 0; k < KK; ++k) { accE[k] = pe; accA[k] = pa; }

    // continuation: c = C..2C-1 over (x_j - x_i), float4-vectorized smem reads
    for (int c4 = 0; c4 < C4; ++c4) {
        int c = c4 * 4;
        float2 w0 = __ldg(&wEA[(C + c + 0) * OP + og]);
        float2 w1 = __ldg(&wEA[(C + c + 1) * OP + og]);
        float2 w2 = __ldg(&wEA[(C + c + 2) * OP + og]);
        float2 w3 = __ldg(&wEA[(C + c + 3) * OP + og]);
#pragma unroll
        for (int k = 0; k < KK; ++k) {
            float4 hd = *reinterpret_cast<const float4*>(&sh_hd[nodeL][k][c]);
            accE[k] = fmaf(w0.x, hd.x, accE[k]);
            accA[k] = fmaf(w0.y, hd.x, accA[k]);
            accE[k] = fmaf(w1.x, hd.y, accE[k]);
            accA[k] = fmaf(w1.y, hd.y, accA[k]);
            accE[k] = fmaf(w2.x, hd.z, accE[k]);
            accA[k] = fmaf(w2.y, hd.z, accA[k]);
            accE[k] = fmaf(w3.x, hd.w, accE[k]);
            accA[k] = fmaf(w3.y, hd.w, accA[k]);
        }
    }
    if (CR) {
        for (int c = C4 * 4; c < C; ++c) {
            float2 w = __ldg(&wEA[(C + c) * OP + og]);
#pragma unroll
            for (int k = 0; k < KK; ++k) {
                float hv = sh_hd[nodeL][k][c];
                accE[k] = fmaf(w.x, hv, accE[k]);
                accA[k] = fmaf(w.y, hv, accA[k]);
            }
        }
    }

    float eb = (og < O) ? __ldg(&be[og]) : 0.f;
    float ab = (og < O) ? __ldg(&ba[og]) : 0.f;
#pragma unroll
    for (int k = 0; k < KK; ++k) {
        sh_e[nodeL][k][og] = __fadd_rn(accE[k], eb);
        sh_a[nodeL][k][og] = __fadd_rn(accA[k], ab);
    }
    __syncthreads();

    if (tid < 2 * O) {
        int nl = tid / O;
        int o = tid - nl * O;
        int n = n0 + nl;
        float la[KK], ex[KK], ea[KK];
#pragma unroll
        for (int k = 0; k < KK; ++k) la[k] = sh_a[nl][k][o];
        float m = la[0];
#pragma unroll
        for (int k = 1; k < KK; ++k) m = fmaxf(m, la[k]);
#pragma unroll
        for (int k = 0; k < KK; ++k)
            ex[k] = expf(__fsub_rn(la[k], m));
        float S = tree_sum16(ex);
#pragma unroll
        for (int k = 0; k < KK; ++k) {
            float av = __fdiv_rn(ex[k], S);
            ea[k] = __fmul_rn(sh_e[nl][k][o], av);
        }
        out[((size_t)(b * NN + n)) * O + o] = tree_sum16(ea);
    }
}

// ---------------- squared norms (XLA warp row-reduction) ----------------
__global__ void __launch_bounds__(256) sqnorm96_kernel(const float* __restrict__ h,
                                                       float* __restrict__ sq) {
    int warp = (blockIdx.x * blockDim.x + threadIdx.x) >> 5;
    int lane = threadIdx.x & 31;
    if (warp >= BB * NN) return;
    const float* r = h + (size_t)warp * 96;
    float x0 = r[lane], x1 = r[lane + 32], x2 = r[lane + 64];
    float p = __fadd_rn(__fadd_rn(__fmul_rn(x0, x0), __fmul_rn(x1, x1)), __fmul_rn(x2, x2));
#pragma unroll
    for (int off = 16; off > 0; off >>= 1)
        p = __fadd_rn(p, __shfl_down_sync(0xffffffffu, p, off));
    if (lane == 0) sq[warp] = p;
}

// ---------------- final pixel-shuffle + column slice ----------------
__global__ void final_kernel(const float* __restrict__ h3, float* __restrict__ out) {
    int t = blockIdx.x * blockDim.x + threadIdx.x;
    if (t >= BB * HIN * WIN) return;
    int w = t % WIN;
    int row = (t / WIN) % HIN;
    int b = t / (WIN * HIN);
    int col = w + 1;
    int j = col / 3, s = col % 3;
    int i = row / 3, r = row % 3;
    int ch = r * 3 + s;
    out[t] = h3[((size_t)(b * NN) + i * WG + j) * 9 + ch];
}

// ---------------- launch ----------------
#define GETSYM(p, sym) do { void* _tmp; cudaGetSymbolAddress(&_tmp, sym); p = _tmp; } while (0)

extern "C" void kernel_launch(void* const* d_in, const int* in_sizes, int n_in,
                              void* d_out, int out_size) {
    const float* guidance = (const float*)d_in[0];
    const float* ini      = (const float*)d_in[1];
    const float* sparse   = (const float*)d_in[2];
    const float* e_w1 = (const float*)d_in[3];
    const float* e_b1 = (const float*)d_in[4];
    const float* a_w1 = (const float*)d_in[5];
    const float* a_b1 = (const float*)d_in[6];
    const float* e_w2 = (const float*)d_in[7];
    const float* e_b2 = (const float*)d_in[8];
    const float* a_w2 = (const float*)d_in[9];
    const float* a_b2 = (const float*)d_in[10];
    const float* e_w3 = (const float*)d_in[11];
    const float* e_b3 = (const float*)d_in[12];
    const float* a_w3 = (const float*)d_in[13];
    const float* a_b3 = (const float*)d_in[14];
    float* out = (float*)d_out;

    void *p_pts0, *p_sq, *p_g81, *p_hA, *p_hB, *p_h3, *p_idx, *p_bd, *p_bi, *p_dist;
    void *p_w1, *p_w2, *p_w3;
    GETSYM(p_pts0, g_pts0); GETSYM(p_sq, g_sq); GETSYM(p_g81, g_g81);
    GETSYM(p_hA, g_hA); GETSYM(p_hB, g_hB); GETSYM(p_h3, g_h3); GETSYM(p_idx, g_idx);
    GETSYM(p_bd, g_bd); GETSYM(p_bi, g_bi); GETSYM(p_dist, g_dist);
    GETSYM(p_w1, g_wEA1); GETSYM(p_w2, g_wEA2); GETSYM(p_w3, g_wEA3);

    float* pts0 = (float*)p_pts0;  float* sqv = (float*)p_sq;  float* g81 = (float*)p_g81;
    float* hA = (float*)p_hA;      float* hB = (float*)p_hB;   float* h3 = (float*)p_h3;
    int* idxb = (int*)p_idx;
    float* bd = (float*)p_bd;      int* bi = (int*)p_bi;
    float* dist = (float*)p_dist;
    float2* wEA1 = (float2*)p_w1;  float2* wEA2 = (float2*)p_w2;  float2* wEA3 = (float2*)p_w3;

    transpose_w2_kernel<<<(162 * 96 + 255) / 256, 256>>>(e_w1, a_w1, wEA1, 162, 96, 96);
    transpose_w2_kernel<<<(192 * 96 + 255) / 256, 256>>>(e_w2, a_w2, wEA2, 192, 96, 96);
    transpose_w2_kernel<<<(192 * 32 + 255) / 256, 256>>>(e_w3, a_w3, wEA3, 192, 9, 32);

    dim3 gN((NN + 127) / 128, BB);
    build_kernel<<<gN, 128>>>(guidance, ini, sparse, pts0, sqv, g81);

    dim3 gK3((NN + 127) / 128, NCH, BB);
    dim3 gM((BB * NN + 127) / 128);
    dim3 gS((BB * NN * 32 + 255) / 256);
    dim3 gE(NN / 2, BB);
    dim3 gD(DT, DT, BB);
    dim3 gSel((NN + 127) / 128, NCH, BB);

    // layer 1
    knn3_kernel<<<gK3, 128>>>(pts0, sqv, bd, bi);
    knn_merge_kernel<<<gM, 128>>>(bd, bi, idxb);
    edge_attn_kernel<81, 96, 96><<<gE, 192>>>(g81, idxb, wEA1, e_b1, a_b1, hA);

    // layer 2
    sqnorm96_kernel<<<gS, 256>>>(hA, sqv);
    knn96_dist_kernel<<<gD, 128>>>(hA, sqv, dist);
    knn96_select_kernel<<<gSel, 128>>>(dist, bd, bi);
    knn_merge_kernel<<<gM, 128>>>(bd, bi, idxb);
    edge_attn_kernel<96, 96, 96><<<gE, 192>>>(hA, idxb, wEA2, e_b2, a_b2, hB);

    // layer 3
    sqnorm96_kernel<<<gS, 256>>>(hB, sqv);
    knn96_dist_kernel<<<gD, 128>>>(hB, sqv, dist);
    knn96_select_kernel<<<gSel, 128>>>(dist, bd, bi);
    knn_merge_kernel<<<gM, 128>>>(bd, bi, idxb);
    edge_attn_kernel<96, 9, 32><<<gE, 64>>>(hB, idxb, wEA3, e_b3, a_b3, h3);

    // output
    final_kernel<<<(BB * HIN * WIN + 255) / 256, 256>>>(h3, out);
}

// round 7
// speedup vs baseline: 1.6216x; 1.0439x over previous
#include <cuda_runtime.h>
#include <math.h>

#define HIN 228
#define WIN 304
#define HG 76
#define WG 102
#define NN 7752
#define BB 2
#define KK 16
#define NCH 8
#define CHSZ (NN / NCH)   // 969
#define DT 61             // 61*128 >= 7752 dist tiles

// ---------------- scratch (device globals; no allocation allowed) ----------------
__device__ float g_pts0[BB * NN * 3];
__device__ float g_sq[BB * NN];
__device__ float g_g81[BB * NN * 81];
__device__ float g_hA[BB * NN * 96];
__device__ float g_hB[BB * NN * 96];
__device__ float g_h3[BB * NN * 9];
__device__ int   g_idx[BB * NN * KK];
__device__ float g_bd[BB * NN * NCH * KK];
__device__ int   g_bi[BB * NN * NCH * KK];
__device__ float g_dist[(size_t)BB * NN * NN];   // D[b][m][q] = dist(query q, cand m)
// interleaved transposed weights: [c][o] -> (we, wa)
__device__ float2 g_wEA1[162 * 96];
__device__ float2 g_wEA2[192 * 96];
__device__ float2 g_wEA3[192 * 32];

// XLA-GPU 16-element reduction tree
__device__ __forceinline__ float tree_sum16(const float* v) {
    float s8[8];
#pragma unroll
    for (int l = 0; l < 8; ++l) s8[l] = __fadd_rn(v[l], v[l + 8]);
    float s4[4];
#pragma unroll
    for (int l = 0; l < 4; ++l) s4[l] = __fadd_rn(s8[l], s8[l + 4]);
    float s2[2];
#pragma unroll
    for (int l = 0; l < 2; ++l) s2[l] = __fadd_rn(s4[l], s4[l + 2]);
    return __fadd_rn(s2[0], s2[1]);
}

// ---------------- build: depth fuse, loc points, guidance graph gather ----------------
__global__ void build_kernel(const float* __restrict__ guidance,
                             const float* __restrict__ ini,
                             const float* __restrict__ sparse,
                             float* __restrict__ pts,
                             float* __restrict__ sq,
                             float* __restrict__ g81) {
    int n = blockIdx.x * blockDim.x + threadIdx.x;
    int b = blockIdx.y;
    if (n >= NN) return;
    int i = n / WG;
    int j = n - i * WG;

    int rd = 3 * i + 1;
    int cd = 3 * j;
    int doff = (b * HIN + rd) * WIN + cd;
    float sp = sparse[doff];
    float iv = ini[doff];
    float mask = (sp > 0.f) ? 1.f : ((sp < 0.f) ? -1.f : 0.f);
    float d = __fadd_rn(__fmul_rn(__fsub_rn(1.f, mask), iv), __fmul_rn(mask, sp));

    const float cxf = 156.52237935402365f;
    const float fxf = 291.31224083868975f;
    const float cyf = 119.22194813310193f;
    const float fyf = 291.3455163549432f;
    float x3 = __fdiv_rn(__fsub_rn((float)j, cxf), fxf);
    float y3 = __fdiv_rn(__fsub_rn((float)i, cyf), fyf);
    float l0 = __fmul_rn(__fmul_rn(x3, d), 3.0f);
    float l1 = __fmul_rn(__fmul_rn(y3, d), 3.0f);
    float l2 = d;

    int base = b * NN + n;
    pts[base * 3 + 0] = l0;
    pts[base * 3 + 1] = l1;
    pts[base * 3 + 2] = l2;
    float p0 = __fmul_rn(l0, l0);
    float p1 = __fmul_rn(l1, l1);
    float p2 = __fmul_rn(l2, l2);
    sq[base] = __fadd_rn(__fadd_rn(p0, p2), p1);

    const float* gb = guidance + (size_t)b * 81 * HIN * WIN;
    float* go = g81 + (size_t)base * 81;
#pragma unroll
    for (int c = 0; c < 81; ++c) {
        int r = 3 * i + (c / 9) - 3;
        int cc = 3 * j + (c % 9) - 4;
        float v = 0.f;
        if (r >= 0 && r < HIN && cc >= 0 && cc < WIN)
            v = gb[(c * HIN + r) * WIN + cc];
        go[c] = v;
    }
}

// ---------------- top-16 insertion (ascending dist; ties keep earlier index) ------
__device__ __forceinline__ void knn_insert(float dist, int index, float* bd, int* bi) {
    if (dist < bd[KK - 1]) {
        bd[KK - 1] = dist;
        bi[KK - 1] = index;
#pragma unroll
        for (int jj = KK - 1; jj > 0; --jj) {
            if (bd[jj] < bd[jj - 1]) {
                float td = bd[jj]; bd[jj] = bd[jj - 1]; bd[jj - 1] = td;
                int ti = bi[jj]; bi[jj] = bi[jj - 1]; bi[jj - 1] = ti;
            }
        }
    }
}

__device__ __forceinline__ float knn_dist(float qsq, float dot, float csq) {
    return __fadd_rn(__fsub_rn(qsq, __fmul_rn(2.0f, dot)), csq);
}

// ---------------- KNN D=3, candidate-chunked (cheap; direct) ----------------
#define KNN_TILE 64

__global__ void __launch_bounds__(128) knn3_kernel(const float* __restrict__ pts,
                                                   const float* __restrict__ sqn,
                                                   float* __restrict__ bdo,
                                                   int* __restrict__ bio) {
    __shared__ float s_c[KNN_TILE * 3];
    __shared__ float s_sq[KNN_TILE];

    int b = blockIdx.z;
    int ch = blockIdx.y;
    int n = blockIdx.x * blockDim.x + threadIdx.x;
    bool valid = (n < NN);

    float q0 = 0.f, q1 = 0.f, q2 = 0.f, qsq = 0.f;
    if (valid) {
        size_t bn = (size_t)(b * NN + n);
        q0 = pts[bn * 3 + 0];
        q1 = pts[bn * 3 + 1];
        q2 = pts[bn * 3 + 2];
        qsq = sqn[bn];
    }

    float bd[KK]; int bi[KK];
#pragma unroll
    for (int k = 0; k < KK; ++k) { bd[k] = 3.0e38f; bi[k] = 0; }

    int mBeg = ch * CHSZ, mEnd = mBeg + CHSZ;
    for (int m0 = mBeg; m0 < mEnd; m0 += KNN_TILE) {
        __syncthreads();
        for (int t = threadIdx.x; t < KNN_TILE * 3; t += blockDim.x) {
            int mm = m0 + t / 3;
            s_c[t] = (mm < mEnd) ? pts[((size_t)b * NN + m0) * 3 + t] : 0.f;
        }
        for (int t = threadIdx.x; t < KNN_TILE; t += blockDim.x) {
            int mm = m0 + t;
            s_sq[t] = (mm < mEnd) ? sqn[b * NN + mm] : 3.0e38f;
        }
        __syncthreads();
        if (valid) {
#pragma unroll 4
            for (int t = 0; t < KNN_TILE; ++t) {
                float a = fmaf(q0, s_c[t * 3 + 0], 0.f);
                a = fmaf(q1, s_c[t * 3 + 1], a);
                a = fmaf(q2, s_c[t * 3 + 2], a);
                knn_insert(knn_dist(qsq, a, s_sq[t]), m0 + t, bd, bi);
            }
        }
    }
    if (valid) {
        size_t base = ((size_t)(b * NN + n) * NCH + ch) * KK;
#pragma unroll
        for (int k = 0; k < KK; ++k) { bdo[base + k] = bd[k]; bio[base + k] = bi[k]; }
    }
}

// ---------------- KNN96 phase 1: symmetric distance matrix, 8x8 register tiling ----
// 128x128 tile per block (ti<=tj), 256 threads, each thread computes an 8x8 pair
// block with rows ty+16r / cols tx+16s. Per-pair dot = serial ascending-c FMA chain
// (bitwise identical to previous kernel). Entry B (D[q][m]) stored directly
// (coalesced); entry A (D[m][q]) staged through smem transpose for coalescing.
__global__ void __launch_bounds__(256) knn96_dist_kernel(const float* __restrict__ pts,
                                                         const float* __restrict__ sqn,
                                                         float* __restrict__ D) {
    extern __shared__ char smem_raw[];
    float4* sQ4 = (float4*)smem_raw;            // [24][128]
    float4* sC4 = sQ4 + 24 * 128;               // [24][128]
    float* sqQ = (float*)(sC4 + 24 * 128);      // [128]
    float* sqC = sqQ + 128;                     // [128]

    int b = blockIdx.z;
    int ti = blockIdx.y, tj = blockIdx.x;
    if (tj < ti) return;
    int I = ti * 128, J = tj * 128;
    int tid = threadIdx.x;
    int tx = tid & 15, ty = tid >> 4;

    const float4* P4 = (const float4*)(pts + (size_t)b * NN * 96);
    for (int idx = tid; idx < 128 * 24; idx += 256) {
        int row = idx & 127;   // consecutive lanes -> consecutive rows (conflict-free STS)
        int c4 = idx >> 7;
        int qr = I + row; int qc = (qr < NN) ? qr : (NN - 1);
        int mr = J + row; int mc = (mr < NN) ? mr : (NN - 1);
        sQ4[c4 * 128 + row] = P4[(size_t)qc * 24 + c4];
        sC4[c4 * 128 + row] = P4[(size_t)mc * 24 + c4];
    }
    if (tid < 128) {
        int qr = I + tid; sqQ[tid] = (qr < NN) ? sqn[b * NN + qr] : 0.f;
        int mr = J + tid; sqC[tid] = (mr < NN) ? sqn[b * NN + mr] : 0.f;
    }
    __syncthreads();

    float acc[8][8];
#pragma unroll
    for (int r = 0; r < 8; ++r)
#pragma unroll
        for (int s = 0; s < 8; ++s) acc[r][s] = 0.f;

    for (int c4 = 0; c4 < 24; ++c4) {
        float4 qv[8], cv[8];
#pragma unroll
        for (int r = 0; r < 8; ++r) qv[r] = sQ4[c4 * 128 + ty + 16 * r];
#pragma unroll
        for (int s = 0; s < 8; ++s) cv[s] = sC4[c4 * 128 + tx + 16 * s];
#pragma unroll
        for (int r = 0; r < 8; ++r)
#pragma unroll
            for (int s = 0; s < 8; ++s) {
                acc[r][s] = fmaf(qv[r].x, cv[s].x, acc[r][s]);
                acc[r][s] = fmaf(qv[r].y, cv[s].y, acc[r][s]);
                acc[r][s] = fmaf(qv[r].z, cv[s].z, acc[r][s]);
                acc[r][s] = fmaf(qv[r].w, cv[s].w, acc[r][s]);
            }
    }

    float sqq[8], sqc[8];
#pragma unroll
    for (int r = 0; r < 8; ++r) sqq[r] = sqQ[ty + 16 * r];
#pragma unroll
    for (int s = 0; s < 8; ++s) sqc[s] = sqC[tx + 16 * s];

    float* Db = D + (size_t)b * NN * NN;

    // entry B: query = m (col), cand = qi (row) -> D[qi][m] = (sq[m]-2dot)+sq[qi]
#pragma unroll
    for (int r = 0; r < 8; ++r) {
        int qi = I + ty + 16 * r;
        if (qi < NN) {
            size_t ro = (size_t)qi * NN;
#pragma unroll
            for (int s = 0; s < 8; ++s) {
                int m = J + tx + 16 * s;
                if (m < NN) Db[ro + m] = knn_dist(sqc[s], acc[r][s], sqq[r]);
            }
        }
    }

    // entry A: query = qi, cand = m -> D[m][qi] = (sq[qi]-2dot)+sq[m], staged transpose
    __syncthreads();
    float* T = (float*)smem_raw;   // [128][132], overwrites sQ4/sC4 (dead)
#pragma unroll
    for (int r = 0; r < 8; ++r)
#pragma unroll
        for (int s = 0; s < 8; ++s)
            T[(tx + 16 * s) * 132 + ty + 16 * r] = knn_dist(sqq[r], acc[r][s], sqc[s]);
    __syncthreads();
    for (int idx = tid; idx < 128 * 128; idx += 256) {
        int mloc = idx >> 7, q = idx & 127;
        int m = J + mloc, qg = I + q;
        if (m < NN && qg < NN)
            Db[(size_t)m * NN + qg] = T[mloc * 132 + q];
    }
}

// ---------------- KNN96 phase 2: chunked top-16 selection over D rows ----------------
__global__ void __launch_bounds__(128) knn96_select_kernel(const float* __restrict__ D,
                                                           float* __restrict__ bdo,
                                                           int* __restrict__ bio) {
    int b = blockIdx.z, ch = blockIdx.y;
    int n = blockIdx.x * blockDim.x + threadIdx.x;
    if (n >= NN) return;
    const float* Db = D + (size_t)b * NN * NN;

    float bd[KK]; int bi[KK];
#pragma unroll
    for (int k = 0; k < KK; ++k) { bd[k] = 3.0e38f; bi[k] = 0; }

    int mBeg = ch * CHSZ, mEnd = mBeg + CHSZ;
    int m = mBeg;
    for (; m + 4 <= mEnd; m += 4) {
        float d0 = Db[(size_t)(m + 0) * NN + n];
        float d1 = Db[(size_t)(m + 1) * NN + n];
        float d2 = Db[(size_t)(m + 2) * NN + n];
        float d3 = Db[(size_t)(m + 3) * NN + n];
        knn_insert(d0, m + 0, bd, bi);
        knn_insert(d1, m + 1, bd, bi);
        knn_insert(d2, m + 2, bd, bi);
        knn_insert(d3, m + 3, bd, bi);
    }
    for (; m < mEnd; ++m)
        knn_insert(Db[(size_t)m * NN + n], m, bd, bi);

    size_t base = ((size_t)(b * NN + n) * NCH + ch) * KK;
#pragma unroll
    for (int k = 0; k < KK; ++k) { bdo[base + k] = bd[k]; bio[base + k] = bi[k]; }
}

// ---------------- stable 8-way merge of per-chunk top-16 lists ----------------
__global__ void knn_merge_kernel(const float* __restrict__ bdall,
                                 const int* __restrict__ biall,
                                 int* __restrict__ out) {
    int q = blockIdx.x * blockDim.x + threadIdx.x;
    if (q >= BB * NN) return;
    int p[NCH];
#pragma unroll
    for (int ch = 0; ch < NCH; ++ch) p[ch] = 0;
    size_t base = (size_t)q * NCH * KK;
#pragma unroll
    for (int s = 0; s < KK; ++s) {
        float best = 3.4e38f;
        int bch = 0;
#pragma unroll
        for (int ch = 0; ch < NCH; ++ch) {
            float dv = bdall[base + ch * KK + p[ch]];
            if (dv < best) { best = dv; bch = ch; }
        }
        out[(size_t)q * KK + s] = biall[base + bch * KK + p[bch]];
        p[bch]++;
    }
}

// ---------------- weight transpose -> interleaved (we, wa), pad output dim ----------------
__global__ void transpose_w2_kernel(const float* __restrict__ we, const float* __restrict__ wa,
                                    float2* __restrict__ wEA, int C2, int O, int OP) {
    int t = blockIdx.x * blockDim.x + threadIdx.x;
    if (t >= C2 * OP) return;
    int c = t / OP;
    int o = t - c * OP;
    float2 v;
    v.x = (o < O) ? we[o * C2 + c] : 0.f;
    v.y = (o < O) ? wa[o * C2 + c] : 0.f;
    wEA[t] = v;
}

// ---------------- per-edge attention with bitwise prefix-halving ----------------
template <int C, int O, int OP>
__global__ void edge_attn_kernel(const float* __restrict__ X,
                                 const int* __restrict__ idx,
                                 const float2* __restrict__ wEA,
                                 const float* __restrict__ be,
                                 const float* __restrict__ ba,
                                 float* __restrict__ out) {
    constexpr int NW = OP / 32;
    constexpr int C4 = C / 4;
    constexpr int CR = C - C4 * 4;
    constexpr int CP = C4 * 4 + (CR ? 4 : 0);
    __shared__ __align__(16) float sh_xi[2][CP];
    __shared__ __align__(16) float sh_hd[2][KK][CP];
    __shared__ float sh_e[2][KK][OP];
    __shared__ float sh_a[2][KK][OP];

    int b = blockIdx.y;
    int n0 = blockIdx.x * 2;
    int tid = threadIdx.x;

    for (int t = tid; t < 2 * C; t += blockDim.x) {
        int nodeL = t / C, c = t - nodeL * C;
        sh_xi[nodeL][c] = X[((size_t)(b * NN + n0 + nodeL)) * C + c];
    }
    for (int t = tid; t < 2 * KK * C; t += blockDim.x) {
        int nodeL = t / (KK * C);
        int r = t - nodeL * (KK * C);
        int k = r / C, c = r - k * C;
        size_t bn = (size_t)(b * NN + n0 + nodeL);
        float xi = X[bn * C + c];
        int j = idx[bn * KK + k];
        sh_hd[nodeL][k][c] = __fsub_rn(X[((size_t)(b * NN + j)) * C + c], xi);
    }
    __syncthreads();

    int warp = tid >> 5, lane = tid & 31;
    int nodeL = warp / NW;
    int og = (warp % NW) * 32 + lane;

    float pe = 0.f, pa = 0.f;
    for (int c = 0; c < C; ++c) {
        float2 w = __ldg(&wEA[c * OP + og]);
        float xv = sh_xi[nodeL][c];
        pe = fmaf(w.x, xv, pe);
        pa = fmaf(w.y, xv, pa);
    }

    float accE[KK], accA[KK];
#pragma unroll
    for (int k = 0; k < KK; ++k) { accE[k] = pe; accA[k] = pa; }

    for (int c4 = 0; c4 < C4; ++c4) {
        int c = c4 * 4;
        float2 w0 = __ldg(&wEA[(C + c + 0) * OP + og]);
        float2 w1 = __ldg(&wEA[(C + c + 1) * OP + og]);
        float2 w2 = __ldg(&wEA[(C + c + 2) * OP + og]);
        float2 w3 = __ldg(&wEA[(C + c + 3) * OP + og]);
#pragma unroll
        for (int k = 0; k < KK; ++k) {
            float4 hd = *reinterpret_cast<const float4*>(&sh_hd[nodeL][k][c]);
            accE[k] = fmaf(w0.x, hd.x, accE[k]);
            accA[k] = fmaf(w0.y, hd.x, accA[k]);
            accE[k] = fmaf(w1.x, hd.y, accE[k]);
            accA[k] = fmaf(w1.y, hd.y, accA[k]);
            accE[k] = fmaf(w2.x, hd.z, accE[k]);
            accA[k] = fmaf(w2.y, hd.z, accA[k]);
            accE[k] = fmaf(w3.x, hd.w, accE[k]);
            accA[k] = fmaf(w3.y, hd.w, accA[k]);
        }
    }
    if (CR) {
        for (int c = C4 * 4; c < C; ++c) {
            float2 w = __ldg(&wEA[(C + c) * OP + og]);
#pragma unroll
            for (int k = 0; k < KK; ++k) {
                float hv = sh_hd[nodeL][k][c];
                accE[k] = fmaf(w.x, hv, accE[k]);
                accA[k] = fmaf(w.y, hv, accA[k]);
            }
        }
    }

    float eb = (og < O) ? __ldg(&be[og]) : 0.f;
    float ab = (og < O) ? __ldg(&ba[og]) : 0.f;
#pragma unroll
    for (int k = 0; k < KK; ++k) {
        sh_e[nodeL][k][og] = __fadd_rn(accE[k], eb);
        sh_a[nodeL][k][og] = __fadd_rn(accA[k], ab);
    }
    __syncthreads();

    if (tid < 2 * O) {
        int nl = tid / O;
        int o = tid - nl * O;
        int n = n0 + nl;
        float la[KK], ex[KK], ea[KK];
#pragma unroll
        for (int k = 0; k < KK; ++k) la[k] = sh_a[nl][k][o];
        float m = la[0];
#pragma unroll
        for (int k = 1; k < KK; ++k) m = fmaxf(m, la[k]);
#pragma unroll
        for (int k = 0; k < KK; ++k)
            ex[k] = expf(__fsub_rn(la[k], m));
        float S = tree_sum16(ex);
#pragma unroll
        for (int k = 0; k < KK; ++k) {
            float av = __fdiv_rn(ex[k], S);
            ea[k] = __fmul_rn(sh_e[nl][k][o], av);
        }
        out[((size_t)(b * NN + n)) * O + o] = tree_sum16(ea);
    }
}

// ---------------- squared norms (XLA warp row-reduction) ----------------
__global__ void __launch_bounds__(256) sqnorm96_kernel(const float* __restrict__ h,
                                                       float* __restrict__ sq) {
    int warp = (blockIdx.x * blockDim.x + threadIdx.x) >> 5;
    int lane = threadIdx.x & 31;
    if (warp >= BB * NN) return;
    const float* r = h + (size_t)warp * 96;
    float x0 = r[lane], x1 = r[lane + 32], x2 = r[lane + 64];
    float p = __fadd_rn(__fadd_rn(__fmul_rn(x0, x0), __fmul_rn(x1, x1)), __fmul_rn(x2, x2));
#pragma unroll
    for (int off = 16; off > 0; off >>= 1)
        p = __fadd_rn(p, __shfl_down_sync(0xffffffffu, p, off));
    if (lane == 0) sq[warp] = p;
}

// ---------------- final pixel-shuffle + column slice ----------------
__global__ void final_kernel(const float* __restrict__ h3, float* __restrict__ out) {
    int t = blockIdx.x * blockDim.x + threadIdx.x;
    if (t >= BB * HIN * WIN) return;
    int w = t % WIN;
    int row = (t / WIN) % HIN;
    int b = t / (WIN * HIN);
    int col = w + 1;
    int j = col / 3, s = col % 3;
    int i = row / 3, r = row % 3;
    int ch = r * 3 + s;
    out[t] = h3[((size_t)(b * NN) + i * WG + j) * 9 + ch];
}

// ---------------- launch ----------------
#define GETSYM(p, sym) do { void* _tmp; cudaGetSymbolAddress(&_tmp, sym); p = _tmp; } while (0)

#define DIST_SMEM (24 * 128 * 16 * 2 + 2 * 128 * 4)   // 99328 bytes

extern "C" void kernel_launch(void* const* d_in, const int* in_sizes, int n_in,
                              void* d_out, int out_size) {
    const float* guidance = (const float*)d_in[0];
    const float* ini      = (const float*)d_in[1];
    const float* sparse   = (const float*)d_in[2];
    const float* e_w1 = (const float*)d_in[3];
    const float* e_b1 = (const float*)d_in[4];
    const float* a_w1 = (const float*)d_in[5];
    const float* a_b1 = (const float*)d_in[6];
    const float* e_w2 = (const float*)d_in[7];
    const float* e_b2 = (const float*)d_in[8];
    const float* a_w2 = (const float*)d_in[9];
    const float* a_b2 = (const float*)d_in[10];
    const float* e_w3 = (const float*)d_in[11];
    const float* e_b3 = (const float*)d_in[12];
    const float* a_w3 = (const float*)d_in[13];
    const float* a_b3 = (const float*)d_in[14];
    float* out = (float*)d_out;

    void *p_pts0, *p_sq, *p_g81, *p_hA, *p_hB, *p_h3, *p_idx, *p_bd, *p_bi, *p_dist;
    void *p_w1, *p_w2, *p_w3;
    GETSYM(p_pts0, g_pts0); GETSYM(p_sq, g_sq); GETSYM(p_g81, g_g81);
    GETSYM(p_hA, g_hA); GETSYM(p_hB, g_hB); GETSYM(p_h3, g_h3); GETSYM(p_idx, g_idx);
    GETSYM(p_bd, g_bd); GETSYM(p_bi, g_bi); GETSYM(p_dist, g_dist);
    GETSYM(p_w1, g_wEA1); GETSYM(p_w2, g_wEA2); GETSYM(p_w3, g_wEA3);

    float* pts0 = (float*)p_pts0;  float* sqv = (float*)p_sq;  float* g81 = (float*)p_g81;
    float* hA = (float*)p_hA;      float* hB = (float*)p_hB;   float* h3 = (float*)p_h3;
    int* idxb = (int*)p_idx;
    float* bd = (float*)p_bd;      int* bi = (int*)p_bi;
    float* dist = (float*)p_dist;
    float2* wEA1 = (float2*)p_w1;  float2* wEA2 = (float2*)p_w2;  float2* wEA3 = (float2*)p_w3;

    static int smem_set = 0;
    if (!smem_set) {
        cudaFuncSetAttribute(knn96_dist_kernel,
                             cudaFuncAttributeMaxDynamicSharedMemorySize, DIST_SMEM);
        smem_set = 1;
    }

    transpose_w2_kernel<<<(162 * 96 + 255) / 256, 256>>>(e_w1, a_w1, wEA1, 162, 96, 96);
    transpose_w2_kernel<<<(192 * 96 + 255) / 256, 256>>>(e_w2, a_w2, wEA2, 192, 96, 96);
    transpose_w2_kernel<<<(192 * 32 + 255) / 256, 256>>>(e_w3, a_w3, wEA3, 192, 9, 32);

    dim3 gN((NN + 127) / 128, BB);
    build_kernel<<<gN, 128>>>(guidance, ini, sparse, pts0, sqv, g81);

    dim3 gK3((NN + 127) / 128, NCH, BB);
    dim3 gM((BB * NN + 127) / 128);
    dim3 gS((BB * NN * 32 + 255) / 256);
    dim3 gE(NN / 2, BB);
    dim3 gD(DT, DT, BB);
    dim3 gSel((NN + 127) / 128, NCH, BB);

    // layer 1
    knn3_kernel<<<gK3, 128>>>(pts0, sqv, bd, bi);
    knn_merge_kernel<<<gM, 128>>>(bd, bi, idxb);
    edge_attn_kernel<81, 96, 96><<<gE, 192>>>(g81, idxb, wEA1, e_b1, a_b1, hA);

    // layer 2
    sqnorm96_kernel<<<gS, 256>>>(hA, sqv);
    knn96_dist_kernel<<<gD, 256, DIST_SMEM>>>(hA, sqv, dist);
    knn96_select_kernel<<<gSel, 128>>>(dist, bd, bi);
    knn_merge_kernel<<<gM, 128>>>(bd, bi, idxb);
    edge_attn_kernel<96, 96, 96><<<gE, 192>>>(hA, idxb, wEA2, e_b2, a_b2, hB);

    // layer 3
    sqnorm96_kernel<<<gS, 256>>>(hB, sqv);
    knn96_dist_kernel<<<gD, 256, DIST_SMEM>>>(hB, sqv, dist);
    knn96_select_kernel<<<gSel, 128>>>(dist, bd, bi);
    knn_merge_kernel<<<gM, 128>>>(bd, bi, idxb);
    edge_attn_kernel<96, 9, 32><<<gE, 64>>>(hB, idxb, wEA3, e_b3, a_b3, h3);

    // output
    final_kernel<<<(BB * HIN * WIN + 255) / 256, 256>>>(h3, out);
}